// round 10
// baseline (speedup 1.0000x reference)
#include <cuda_runtime.h>
#include <cstdint>

#define NN 50000
#define NE 600000
#define DD 128
#define DE 32

typedef unsigned long long u64;

// Scratch (device globals — no allocation allowed)
__device__ float g_agg[NN * DD];
__device__ float g_h[NN * DD];
__device__ float g_t[NN * DD];
__device__ float g_eap[(size_t)NE * DE];     // permuted edge_attr (77 MB)
__device__ int   g_rowptr[NN + 1];
__device__ int   g_woff[NN];
__device__ int   g_cnt[NN];
__device__ int   g_srcp[NE];
__device__ int   g_dstp[NE];
__device__ int   g_eidx[NE];

// ---- packed fp32x2 helpers ----
__device__ __forceinline__ u64 ffma2(u64 a, u64 b, u64 c) {
    u64 d;
    asm("fma.rn.f32x2 %0, %1, %2, %3;" : "=l"(d) : "l"(a), "l"(b), "l"(c));
    return d;
}
__device__ __forceinline__ u64 pack2(float lo, float hi) {
    u64 d;
    asm("mov.b64 %0, {%1, %2};" : "=l"(d) : "f"(lo), "f"(hi));
    return d;
}
__device__ __forceinline__ void unpack2(u64 v, float& lo, float& hi) {
    asm("mov.b64 {%0, %1}, %2;" : "=f"(lo), "=f"(hi) : "l"(v));
}

// ===========================================================================
// CSR build (unchanged)
// ===========================================================================
__global__ void zero_cnt_kernel() {
    int i = blockIdx.x * blockDim.x + threadIdx.x;
    if (i < NN) g_cnt[i] = 0;
}

__global__ void hist_kernel(const int* __restrict__ ei) {
    int i = blockIdx.x * blockDim.x + threadIdx.x;
    if (i < NE) atomicAdd(&g_cnt[ei[NE + i]], 1);
}

__global__ void scan_kernel() {
    __shared__ int s[1024];
    const int tid = threadIdx.x;
    const int CH = (NN + 1023) / 1024;
    const int base = tid * CH;
    const int end = min(base + CH, NN);
    int tot = 0;
    for (int i = base; i < end; i++) tot += g_cnt[i];
    s[tid] = tot;
    __syncthreads();
#pragma unroll
    for (int off = 1; off < 1024; off <<= 1) {
        int t = (tid >= off) ? s[tid - off] : 0;
        __syncthreads();
        s[tid] += t;
        __syncthreads();
    }
    int run = s[tid] - tot;
    for (int i = base; i < end; i++) {
        int v = g_cnt[i];
        g_rowptr[i] = run;
        g_woff[i] = run;
        run += v;
    }
    if (end == NN) g_rowptr[NN] = run;
}

__global__ void scatter_kernel(const int* __restrict__ ei) {
    int i = blockIdx.x * blockDim.x + threadIdx.x;
    if (i < NE) {
        int d = ei[NE + i];
        int p = atomicAdd(&g_woff[d], 1);
        g_srcp[p] = ei[i];
        g_dstp[p] = d;
        g_eidx[p] = i;
    }
}

__global__ void permute_ea_kernel(const float4* __restrict__ ea4) {
    long long t = (long long)blockIdx.x * blockDim.x + threadIdx.x;
    if (t < (long long)NE * 8) {
        long long i = t >> 3;
        int c = (int)(t & 7);
        int e = g_eidx[i];
        ((float4*)g_eap)[t] = ea4[(long long)e * 8 + c];
    }
}

// ===========================================================================
// Fused edge kernel (unchanged from R6): GEMM + segmented RED into agg
// ===========================================================================
__global__ void __launch_bounds__(256, 2)
edge_fused_kernel(const float* __restrict__ xin,
                  const float* __restrict__ we, const float* __restrict__ be,
                  float* __restrict__ agg) {
    __shared__ float Ea[DE][130];
    __shared__ float Bs[DE][DD];

    const int tid = threadIdx.x;
    const int tx = tid & 15;
    const int ty = tid >> 4;
    const long long i0 = (long long)blockIdx.x * 128;

#pragma unroll
    for (int l = 0; l < 4; l++) {
        int idx = tid + l * 256;
        int r  = idx >> 3;
        int c4 = idx & 7;
        float4 v = make_float4(0.f, 0.f, 0.f, 0.f);
        long long gi = i0 + r;
        if (gi < NE) v = ((const float4*)g_eap)[gi * 8 + c4];
        Ea[c4 * 4 + 0][r] = v.x;
        Ea[c4 * 4 + 1][r] = v.y;
        Ea[c4 * 4 + 2][r] = v.z;
        Ea[c4 * 4 + 3][r] = v.w;
        ((float4*)&Bs[idx >> 5][0])[idx & 31] = ((const float4*)we)[idx];
    }
    __syncthreads();

    u64 acc2[4][8];
#pragma unroll
    for (int i = 0; i < 4; i++)
#pragma unroll
        for (int j = 0; j < 8; j++) acc2[i][j] = 0ULL;

#pragma unroll 8
    for (int k = 0; k < DE; k++) {
        const u64* ap = (const u64*)&Ea[k][ty * 8];
        u64 av[4] = {ap[0], ap[1], ap[2], ap[3]};
        float4 b0 = ((const float4*)&Bs[k][0])[tx * 2];
        float4 b1 = ((const float4*)&Bs[k][0])[tx * 2 + 1];
        u64 bd[8];
        bd[0] = pack2(b0.x, b0.x); bd[1] = pack2(b0.y, b0.y);
        bd[2] = pack2(b0.z, b0.z); bd[3] = pack2(b0.w, b0.w);
        bd[4] = pack2(b1.x, b1.x); bd[5] = pack2(b1.y, b1.y);
        bd[6] = pack2(b1.z, b1.z); bd[7] = pack2(b1.w, b1.w);
#pragma unroll
        for (int i = 0; i < 4; i++)
#pragma unroll
            for (int j = 0; j < 8; j++)
                acc2[i][j] = ffma2(av[i], bd[j], acc2[i][j]);
    }

    float4 bb0 = ((const float4*)be)[tx * 2];
    float4 bb1 = ((const float4*)be)[tx * 2 + 1];
    float bvv[8] = {bb0.x, bb0.y, bb0.z, bb0.w, bb1.x, bb1.y, bb1.z, bb1.w};

    int d_cur = -1;
    float sum[8];
#pragma unroll
    for (int rr = 0; rr < 8; rr++) {
        long long gi = i0 + ty * 8 + rr;
        if (gi < NE) {
            int d = g_dstp[gi];
            int src = g_srcp[gi];
            int i2 = rr >> 1;
            float o[8];
#pragma unroll
            for (int j = 0; j < 8; j++) {
                float lo, hi;
                unpack2(acc2[i2][j], lo, hi);
                o[j] = (rr & 1) ? hi : lo;
            }
            float4 xv0 = ((const float4*)xin)[(long long)src * 32 + tx * 2];
            float4 xv1 = ((const float4*)xin)[(long long)src * 32 + tx * 2 + 1];
            float xr[8] = {xv0.x, xv0.y, xv0.z, xv0.w, xv1.x, xv1.y, xv1.z, xv1.w};
            float res[8];
#pragma unroll
            for (int j = 0; j < 8; j++)
                res[j] = fmaxf(o[j] + bvv[j] + xr[j], 0.f);
            if (d != d_cur) {
                if (d_cur >= 0) {
                    float* p = agg + (long long)d_cur * DD + tx * 8;
                    asm volatile("red.global.add.v4.f32 [%0], {%1,%2,%3,%4};"
                                 :: "l"(p), "f"(sum[0]), "f"(sum[1]), "f"(sum[2]), "f"(sum[3]) : "memory");
                    asm volatile("red.global.add.v4.f32 [%0], {%1,%2,%3,%4};"
                                 :: "l"(p + 4), "f"(sum[4]), "f"(sum[5]), "f"(sum[6]), "f"(sum[7]) : "memory");
                }
                d_cur = d;
#pragma unroll
                for (int j = 0; j < 8; j++) sum[j] = res[j];
            } else {
#pragma unroll
                for (int j = 0; j < 8; j++) sum[j] += res[j];
            }
        }
    }
    if (d_cur >= 0) {
        float* p = agg + (long long)d_cur * DD + tx * 8;
        asm volatile("red.global.add.v4.f32 [%0], {%1,%2,%3,%4};"
                     :: "l"(p), "f"(sum[0]), "f"(sum[1]), "f"(sum[2]), "f"(sum[3]) : "memory");
        asm volatile("red.global.add.v4.f32 [%0], {%1,%2,%3,%4};"
                     :: "l"(p + 4), "f"(sum[4]), "f"(sum[5]), "f"(sum[6]), "f"(sum[7]) : "memory");
    }
}

__global__ void copy4_kernel(const float4* __restrict__ s, float4* __restrict__ d, int n4) {
    int i = blockIdx.x * blockDim.x + threadIdx.x;
    if (i < n4) d[i] = s[i];
}

// ===========================================================================
// Tiled SGEMM v3 (f32x2, double-buffered, pre-duplicated B):
// out[M,128] = act(A[M,128] @ W[128,128] + bias)
// BM=128, BN=128, BK=16, 256 threads, 8x8 micro-tile.
// DupB[k][n] holds {W[k][n], W[k][n]} as u64 -> inner loop has no packing.
// One __syncthreads per tile; next tile's global loads overlap compute.
// ===========================================================================
template <bool RELU>
__global__ void __launch_bounds__(256, 2)
mlp_gemm(const float* __restrict__ A, const float* __restrict__ W,
         const float* __restrict__ bias, float* __restrict__ out, int M) {
    __shared__ float As[2][16][128];    // 16 KB
    __shared__ u64   DupB[2][16][128];  // 32 KB

    const int tid = threadIdx.x;
    const int tx = tid & 15;
    const int ty = tid >> 4;
    const int row0 = blockIdx.x * 128;

    // per-thread load indices (constant across tiles)
    const int ar0 = tid >> 2;            // A row for l=0 (0..63)
    const int ac  = tid & 3;             // A float4-col within tile
    const int bk0 = tid >> 5;            // B k for l=0 (0..7)
    const int bn  = tid & 31;            // B float4-col (0..31)

    u64 acc2[4][8];
#pragma unroll
    for (int i = 0; i < 4; i++)
#pragma unroll
        for (int j = 0; j < 8; j++) acc2[i][j] = 0ULL;

    float4 aReg[2], bReg[2];
    // ---- prefetch tile 0 into registers ----
#pragma unroll
    for (int l = 0; l < 2; l++) {
        int gr = row0 + ar0 + l * 64;
        aReg[l] = (gr < M) ? ((const float4*)A)[(long long)gr * 32 + ac]
                           : make_float4(0.f, 0.f, 0.f, 0.f);
        bReg[l] = ((const float4*)W)[(bk0 + l * 8) * 32 + bn];
    }
    // ---- store tile 0 ----
#pragma unroll
    for (int l = 0; l < 2; l++) {
        int r = ar0 + l * 64;
        As[0][ac * 4 + 0][r] = aReg[l].x;
        As[0][ac * 4 + 1][r] = aReg[l].y;
        As[0][ac * 4 + 2][r] = aReg[l].z;
        As[0][ac * 4 + 3][r] = aReg[l].w;
        int k = bk0 + l * 8;
        float4* db = (float4*)&DupB[0][k][bn * 4];
        db[0] = make_float4(bReg[l].x, bReg[l].x, bReg[l].y, bReg[l].y);
        db[1] = make_float4(bReg[l].z, bReg[l].z, bReg[l].w, bReg[l].w);
    }
    __syncthreads();

    for (int t = 0; t < 8; t++) {
        const int buf = t & 1;
        // prefetch tile t+1
        if (t < 7) {
#pragma unroll
            for (int l = 0; l < 2; l++) {
                int gr = row0 + ar0 + l * 64;
                aReg[l] = (gr < M) ? ((const float4*)A)[(long long)gr * 32 + (t + 1) * 4 + ac]
                                   : make_float4(0.f, 0.f, 0.f, 0.f);
                bReg[l] = ((const float4*)W)[((t + 1) * 16 + bk0 + l * 8) * 32 + bn];
            }
        }
        // compute on buf
#pragma unroll
        for (int k = 0; k < 16; k++) {
            const u64* ap = (const u64*)&As[buf][k][ty * 8];
            u64 av[4] = {ap[0], ap[1], ap[2], ap[3]};
            const u64* bp = &DupB[buf][k][tx * 8];
#pragma unroll
            for (int i = 0; i < 4; i++)
#pragma unroll
                for (int j = 0; j < 8; j++)
                    acc2[i][j] = ffma2(av[i], bp[j], acc2[i][j]);
        }
        // store tile t+1 into other buffer
        if (t < 7) {
            const int nbuf = buf ^ 1;
#pragma unroll
            for (int l = 0; l < 2; l++) {
                int r = ar0 + l * 64;
                As[nbuf][ac * 4 + 0][r] = aReg[l].x;
                As[nbuf][ac * 4 + 1][r] = aReg[l].y;
                As[nbuf][ac * 4 + 2][r] = aReg[l].z;
                As[nbuf][ac * 4 + 3][r] = aReg[l].w;
                int k = bk0 + l * 8;
                float4* db = (float4*)&DupB[nbuf][k][bn * 4];
                db[0] = make_float4(bReg[l].x, bReg[l].x, bReg[l].y, bReg[l].y);
                db[1] = make_float4(bReg[l].z, bReg[l].z, bReg[l].w, bReg[l].w);
            }
            __syncthreads();
        }
    }

    float4 bb0 = ((const float4*)bias)[tx * 2];
    float4 bb1 = ((const float4*)bias)[tx * 2 + 1];
    float bvv[8] = {bb0.x, bb0.y, bb0.z, bb0.w, bb1.x, bb1.y, bb1.z, bb1.w};
#pragma unroll
    for (int i2 = 0; i2 < 4; i2++) {
        float o0[8], o1[8];
#pragma unroll
        for (int j = 0; j < 8; j++) {
            float lo, hi;
            unpack2(acc2[i2][j], lo, hi);
            lo += bvv[j]; hi += bvv[j];
            if (RELU) { lo = fmaxf(lo, 0.f); hi = fmaxf(hi, 0.f); }
            o0[j] = lo; o1[j] = hi;
        }
        int r0 = row0 + ty * 8 + 2 * i2;
        if (r0 < M) {
            float4* po = (float4*)(out + (long long)r0 * DD);
            po[tx * 2]     = make_float4(o0[0], o0[1], o0[2], o0[3]);
            po[tx * 2 + 1] = make_float4(o0[4], o0[5], o0[6], o0[7]);
        }
        if (r0 + 1 < M) {
            float4* po = (float4*)(out + (long long)(r0 + 1) * DD);
            po[tx * 2]     = make_float4(o1[0], o1[1], o1[2], o1[3]);
            po[tx * 2 + 1] = make_float4(o1[4], o1[5], o1[6], o1[7]);
        }
    }
}

// ---------------------------------------------------------------------------
extern "C" void kernel_launch(void* const* d_in, const int* in_sizes, int n_in,
                              void* d_out, int out_size) {
    const float* x    = (const float*)d_in[0];
    const int*   ei   = (const int*)d_in[1];      // int32
    const float* ea   = (const float*)d_in[2];
    const float* w1_0 = (const float*)d_in[3];
    const float* b1_0 = (const float*)d_in[4];
    const float* w2_0 = (const float*)d_in[5];
    const float* b2_0 = (const float*)d_in[6];
    const float* we_0 = (const float*)d_in[7];
    const float* be_0 = (const float*)d_in[8];
    const float* w1_1 = (const float*)d_in[9];
    const float* b1_1 = (const float*)d_in[10];
    const float* w2_1 = (const float*)d_in[11];
    const float* b2_1 = (const float*)d_in[12];
    const float* we_1 = (const float*)d_in[13];
    const float* be_1 = (const float*)d_in[14];
    const float* fc1w = (const float*)d_in[15];
    const float* fc1b = (const float*)d_in[16];
    const float* fc2w = (const float*)d_in[17];
    const float* fc2b = (const float*)d_in[18];
    float* out = (float*)d_out;

    float *agg, *h, *t;
    cudaGetSymbolAddress((void**)&agg, g_agg);
    cudaGetSymbolAddress((void**)&h,   g_h);
    cudaGetSymbolAddress((void**)&t,   g_t);

    const int n4 = NN * (DD / 4);
    const int copyBlocks = (n4 + 255) / 256;
    const int nodeBlocks = (NN + 255) / 256;
    const int edgeThreadBlocks = (NE + 255) / 256;
    const int permBlocks = (int)(((long long)NE * 8 + 255) / 256);
    const int fusedBlocks = (NE + 127) / 128;
    const int gemmBlocks = (NN + 127) / 128;          // 391

    // ---- CSR build (once; reused by both layers) ----
    zero_cnt_kernel<<<nodeBlocks, 256>>>();
    hist_kernel<<<edgeThreadBlocks, 256>>>(ei);
    scan_kernel<<<1, 1024>>>();
    scatter_kernel<<<edgeThreadBlocks, 256>>>(ei);
    permute_ea_kernel<<<permBlocks, 256>>>((const float4*)ea);

    // ---- Layer 0 ----
    copy4_kernel<<<copyBlocks, 256>>>((const float4*)x, (float4*)agg, n4);
    edge_fused_kernel<<<fusedBlocks, 256>>>(x, we_0, be_0, agg);
    mlp_gemm<true><<<gemmBlocks, 256>>>(agg, w1_0, b1_0, t, NN);
    mlp_gemm<true><<<gemmBlocks, 256>>>(t, w2_0, b2_0, h, NN);

    // ---- Layer 1 ----
    copy4_kernel<<<copyBlocks, 256>>>((const float4*)h, (float4*)agg, n4);
    edge_fused_kernel<<<fusedBlocks, 256>>>(h, we_1, be_1, agg);
    mlp_gemm<true><<<gemmBlocks, 256>>>(agg, w1_1, b1_1, t, NN);
    mlp_gemm<true><<<gemmBlocks, 256>>>(t, w2_1, b2_1, h, NN);

    // ---- Head ----
    mlp_gemm<true><<<gemmBlocks, 256>>>(h, fc1w, fc1b, t, NN);
    mlp_gemm<false><<<gemmBlocks, 256>>>(t, fc2w, fc2b, out, NN);
}

// round 11
// speedup vs baseline: 2.5106x; 2.5106x over previous
#include <cuda_runtime.h>
#include <cstdint>

#define NN 50000
#define NE 600000
#define DD 128
#define DE 32

typedef unsigned long long u64;

// Scratch (device globals — no allocation allowed)
__device__ float g_agg[NN * DD];
__device__ float g_h[NN * DD];
__device__ float g_eap[(size_t)NE * DE];     // permuted edge_attr (77 MB)
__device__ int   g_rowptr[NN + 1];
__device__ int   g_woff[NN];
__device__ int   g_cnt[NN];
__device__ int   g_srcp[NE];
__device__ int   g_dstp[NE];
__device__ int   g_eidx[NE];

// ---- packed fp32x2 helpers ----
__device__ __forceinline__ u64 ffma2(u64 a, u64 b, u64 c) {
    u64 d;
    asm("fma.rn.f32x2 %0, %1, %2, %3;" : "=l"(d) : "l"(a), "l"(b), "l"(c));
    return d;
}
__device__ __forceinline__ u64 pack2(float lo, float hi) {
    u64 d;
    asm("mov.b64 %0, {%1, %2};" : "=l"(d) : "f"(lo), "f"(hi));
    return d;
}
__device__ __forceinline__ void unpack2(u64 v, float& lo, float& hi) {
    asm("mov.b64 {%0, %1}, %2;" : "=f"(lo), "=f"(hi) : "l"(v));
}

// ===========================================================================
// CSR build (unchanged)
// ===========================================================================
__global__ void zero_cnt_kernel() {
    int i = blockIdx.x * blockDim.x + threadIdx.x;
    if (i < NN) g_cnt[i] = 0;
}

__global__ void hist_kernel(const int* __restrict__ ei) {
    int i = blockIdx.x * blockDim.x + threadIdx.x;
    if (i < NE) atomicAdd(&g_cnt[ei[NE + i]], 1);
}

__global__ void scan_kernel() {
    __shared__ int s[1024];
    const int tid = threadIdx.x;
    const int CH = (NN + 1023) / 1024;
    const int base = tid * CH;
    const int end = min(base + CH, NN);
    int tot = 0;
    for (int i = base; i < end; i++) tot += g_cnt[i];
    s[tid] = tot;
    __syncthreads();
#pragma unroll
    for (int off = 1; off < 1024; off <<= 1) {
        int t = (tid >= off) ? s[tid - off] : 0;
        __syncthreads();
        s[tid] += t;
        __syncthreads();
    }
    int run = s[tid] - tot;
    for (int i = base; i < end; i++) {
        int v = g_cnt[i];
        g_rowptr[i] = run;
        g_woff[i] = run;
        run += v;
    }
    if (end == NN) g_rowptr[NN] = run;
}

__global__ void scatter_kernel(const int* __restrict__ ei) {
    int i = blockIdx.x * blockDim.x + threadIdx.x;
    if (i < NE) {
        int d = ei[NE + i];
        int p = atomicAdd(&g_woff[d], 1);
        g_srcp[p] = ei[i];
        g_dstp[p] = d;
        g_eidx[p] = i;
    }
}

__global__ void permute_ea_kernel(const float4* __restrict__ ea4) {
    long long t = (long long)blockIdx.x * blockDim.x + threadIdx.x;
    if (t < (long long)NE * 8) {
        long long i = t >> 3;
        int c = (int)(t & 7);
        int e = g_eidx[i];
        ((float4*)g_eap)[t] = ea4[(long long)e * 8 + c];
    }
}

// ===========================================================================
// Fused edge kernel (unchanged from R6): GEMM + segmented RED into agg
// ===========================================================================
__global__ void __launch_bounds__(256, 2)
edge_fused_kernel(const float* __restrict__ xin,
                  const float* __restrict__ we, const float* __restrict__ be,
                  float* __restrict__ agg) {
    __shared__ float Ea[DE][130];
    __shared__ float Bs[DE][DD];

    const int tid = threadIdx.x;
    const int tx = tid & 15;
    const int ty = tid >> 4;
    const long long i0 = (long long)blockIdx.x * 128;

#pragma unroll
    for (int l = 0; l < 4; l++) {
        int idx = tid + l * 256;
        int r  = idx >> 3;
        int c4 = idx & 7;
        float4 v = make_float4(0.f, 0.f, 0.f, 0.f);
        long long gi = i0 + r;
        if (gi < NE) v = ((const float4*)g_eap)[gi * 8 + c4];
        Ea[c4 * 4 + 0][r] = v.x;
        Ea[c4 * 4 + 1][r] = v.y;
        Ea[c4 * 4 + 2][r] = v.z;
        Ea[c4 * 4 + 3][r] = v.w;
        ((float4*)&Bs[idx >> 5][0])[idx & 31] = ((const float4*)we)[idx];
    }
    __syncthreads();

    u64 acc2[4][8];
#pragma unroll
    for (int i = 0; i < 4; i++)
#pragma unroll
        for (int j = 0; j < 8; j++) acc2[i][j] = 0ULL;

#pragma unroll 8
    for (int k = 0; k < DE; k++) {
        const u64* ap = (const u64*)&Ea[k][ty * 8];
        u64 av[4] = {ap[0], ap[1], ap[2], ap[3]};
        float4 b0 = ((const float4*)&Bs[k][0])[tx * 2];
        float4 b1 = ((const float4*)&Bs[k][0])[tx * 2 + 1];
        u64 bd[8];
        bd[0] = pack2(b0.x, b0.x); bd[1] = pack2(b0.y, b0.y);
        bd[2] = pack2(b0.z, b0.z); bd[3] = pack2(b0.w, b0.w);
        bd[4] = pack2(b1.x, b1.x); bd[5] = pack2(b1.y, b1.y);
        bd[6] = pack2(b1.z, b1.z); bd[7] = pack2(b1.w, b1.w);
#pragma unroll
        for (int i = 0; i < 4; i++)
#pragma unroll
            for (int j = 0; j < 8; j++)
                acc2[i][j] = ffma2(av[i], bd[j], acc2[i][j]);
    }

    float4 bb0 = ((const float4*)be)[tx * 2];
    float4 bb1 = ((const float4*)be)[tx * 2 + 1];
    float bvv[8] = {bb0.x, bb0.y, bb0.z, bb0.w, bb1.x, bb1.y, bb1.z, bb1.w};

    int d_cur = -1;
    float sum[8];
#pragma unroll
    for (int rr = 0; rr < 8; rr++) {
        long long gi = i0 + ty * 8 + rr;
        if (gi < NE) {
            int d = g_dstp[gi];
            int src = g_srcp[gi];
            int i2 = rr >> 1;
            float o[8];
#pragma unroll
            for (int j = 0; j < 8; j++) {
                float lo, hi;
                unpack2(acc2[i2][j], lo, hi);
                o[j] = (rr & 1) ? hi : lo;
            }
            float4 xv0 = ((const float4*)xin)[(long long)src * 32 + tx * 2];
            float4 xv1 = ((const float4*)xin)[(long long)src * 32 + tx * 2 + 1];
            float xr[8] = {xv0.x, xv0.y, xv0.z, xv0.w, xv1.x, xv1.y, xv1.z, xv1.w};
            float res[8];
#pragma unroll
            for (int j = 0; j < 8; j++)
                res[j] = fmaxf(o[j] + bvv[j] + xr[j], 0.f);
            if (d != d_cur) {
                if (d_cur >= 0) {
                    float* p = agg + (long long)d_cur * DD + tx * 8;
                    asm volatile("red.global.add.v4.f32 [%0], {%1,%2,%3,%4};"
                                 :: "l"(p), "f"(sum[0]), "f"(sum[1]), "f"(sum[2]), "f"(sum[3]) : "memory");
                    asm volatile("red.global.add.v4.f32 [%0], {%1,%2,%3,%4};"
                                 :: "l"(p + 4), "f"(sum[4]), "f"(sum[5]), "f"(sum[6]), "f"(sum[7]) : "memory");
                }
                d_cur = d;
#pragma unroll
                for (int j = 0; j < 8; j++) sum[j] = res[j];
            } else {
#pragma unroll
                for (int j = 0; j < 8; j++) sum[j] += res[j];
            }
        }
    }
    if (d_cur >= 0) {
        float* p = agg + (long long)d_cur * DD + tx * 8;
        asm volatile("red.global.add.v4.f32 [%0], {%1,%2,%3,%4};"
                     :: "l"(p), "f"(sum[0]), "f"(sum[1]), "f"(sum[2]), "f"(sum[3]) : "memory");
        asm volatile("red.global.add.v4.f32 [%0], {%1,%2,%3,%4};"
                     :: "l"(p + 4), "f"(sum[4]), "f"(sum[5]), "f"(sum[6]), "f"(sum[7]) : "memory");
    }
}

__global__ void copy4_kernel(const float4* __restrict__ s, float4* __restrict__ d, int n4) {
    int i = blockIdx.x * blockDim.x + threadIdx.x;
    if (i < n4) d[i] = s[i];
}

// ===========================================================================
// Fused 2-GEMM MLP (R6 inner loop, run twice):
//   h1 = relu(A@W1 + b1)   (tile kept in smem)
//   out = act(h1@W2 + b2)
// Block = 128 rows. Dynamic smem: h1[128][128] + As[16][128] + Bs[16][128].
// ===========================================================================
#define MLP2_H1   0
#define MLP2_AS   (128 * 128 * 4)
#define MLP2_BS   (MLP2_AS + 16 * 128 * 4)
#define MLP2_SMEM (MLP2_BS + 16 * 128 * 4)    // 81920 B

template <bool RELU2>
__global__ void __launch_bounds__(256, 2)
mlp2_gemm(const float* __restrict__ A,
          const float* __restrict__ W1, const float* __restrict__ b1,
          const float* __restrict__ W2, const float* __restrict__ b2,
          float* __restrict__ out, int M) {
    extern __shared__ char smem[];
    float* H1 = (float*)(smem + MLP2_H1);               // [128][128]
    float (*As)[128] = (float (*)[128])(smem + MLP2_AS);
    float (*Bs)[128] = (float (*)[128])(smem + MLP2_BS);

    const int tid = threadIdx.x;
    const int tx = tid & 15;
    const int ty = tid >> 4;
    const int row0 = blockIdx.x * 128;

    u64 acc2[4][8];

    // ===================== Stage 1: A(global) @ W1 -> H1(smem) =============
#pragma unroll
    for (int i = 0; i < 4; i++)
#pragma unroll
        for (int j = 0; j < 8; j++) acc2[i][j] = 0ULL;

    for (int k0 = 0; k0 < 128; k0 += 16) {
#pragma unroll
        for (int l = 0; l < 2; l++) {
            int idx = tid + l * 256;
            int r  = idx >> 2;
            int c4 = idx & 3;
            float4 v = make_float4(0.f, 0.f, 0.f, 0.f);
            int grow = row0 + r;
            if (grow < M) v = ((const float4*)A)[(long long)grow * 32 + (k0 >> 2) + c4];
            As[c4 * 4 + 0][r] = v.x;
            As[c4 * 4 + 1][r] = v.y;
            As[c4 * 4 + 2][r] = v.z;
            As[c4 * 4 + 3][r] = v.w;
            int k  = idx >> 5;
            int n4 = idx & 31;
            ((float4*)&Bs[k][0])[n4] = ((const float4*)W1)[(k0 + k) * 32 + n4];
        }
        __syncthreads();
#pragma unroll
        for (int k = 0; k < 16; k++) {
            const u64* ap = (const u64*)&As[k][ty * 8];
            u64 av[4] = {ap[0], ap[1], ap[2], ap[3]};
            float4 v0 = ((const float4*)&Bs[k][0])[tx * 2];
            float4 v1 = ((const float4*)&Bs[k][0])[tx * 2 + 1];
            u64 bd[8];
            bd[0] = pack2(v0.x, v0.x); bd[1] = pack2(v0.y, v0.y);
            bd[2] = pack2(v0.z, v0.z); bd[3] = pack2(v0.w, v0.w);
            bd[4] = pack2(v1.x, v1.x); bd[5] = pack2(v1.y, v1.y);
            bd[6] = pack2(v1.z, v1.z); bd[7] = pack2(v1.w, v1.w);
#pragma unroll
            for (int i = 0; i < 4; i++)
#pragma unroll
                for (int j = 0; j < 8; j++)
                    acc2[i][j] = ffma2(av[i], bd[j], acc2[i][j]);
        }
        __syncthreads();
    }

    // epilogue 1: bias + relu -> H1 (row-major, float4 stores)
    {
        float4 bb0 = ((const float4*)b1)[tx * 2];
        float4 bb1 = ((const float4*)b1)[tx * 2 + 1];
        float bvv[8] = {bb0.x, bb0.y, bb0.z, bb0.w, bb1.x, bb1.y, bb1.z, bb1.w};
#pragma unroll
        for (int i2 = 0; i2 < 4; i2++) {
            float o0[8], o1[8];
#pragma unroll
            for (int j = 0; j < 8; j++) {
                float lo, hi;
                unpack2(acc2[i2][j], lo, hi);
                o0[j] = fmaxf(lo + bvv[j], 0.f);
                o1[j] = fmaxf(hi + bvv[j], 0.f);
            }
            int r0 = ty * 8 + 2 * i2;
            float4* p0 = (float4*)(H1 + r0 * 128);
            p0[tx * 2]     = make_float4(o0[0], o0[1], o0[2], o0[3]);
            p0[tx * 2 + 1] = make_float4(o0[4], o0[5], o0[6], o0[7]);
            float4* p1 = (float4*)(H1 + (r0 + 1) * 128);
            p1[tx * 2]     = make_float4(o1[0], o1[1], o1[2], o1[3]);
            p1[tx * 2 + 1] = make_float4(o1[4], o1[5], o1[6], o1[7]);
        }
    }
    __syncthreads();

    // ===================== Stage 2: H1(smem) @ W2 -> out ===================
#pragma unroll
    for (int i = 0; i < 4; i++)
#pragma unroll
        for (int j = 0; j < 8; j++) acc2[i][j] = 0ULL;

    for (int k0 = 0; k0 < 128; k0 += 16) {
#pragma unroll
        for (int l = 0; l < 2; l++) {
            int idx = tid + l * 256;
            int r  = idx >> 2;
            int c4 = idx & 3;
            float4 v = ((const float4*)H1)[r * 32 + (k0 >> 2) + c4];
            As[c4 * 4 + 0][r] = v.x;
            As[c4 * 4 + 1][r] = v.y;
            As[c4 * 4 + 2][r] = v.z;
            As[c4 * 4 + 3][r] = v.w;
            int k  = idx >> 5;
            int n4 = idx & 31;
            ((float4*)&Bs[k][0])[n4] = ((const float4*)W2)[(k0 + k) * 32 + n4];
        }
        __syncthreads();
#pragma unroll
        for (int k = 0; k < 16; k++) {
            const u64* ap = (const u64*)&As[k][ty * 8];
            u64 av[4] = {ap[0], ap[1], ap[2], ap[3]};
            float4 v0 = ((const float4*)&Bs[k][0])[tx * 2];
            float4 v1 = ((const float4*)&Bs[k][0])[tx * 2 + 1];
            u64 bd[8];
            bd[0] = pack2(v0.x, v0.x); bd[1] = pack2(v0.y, v0.y);
            bd[2] = pack2(v0.z, v0.z); bd[3] = pack2(v0.w, v0.w);
            bd[4] = pack2(v1.x, v1.x); bd[5] = pack2(v1.y, v1.y);
            bd[6] = pack2(v1.z, v1.z); bd[7] = pack2(v1.w, v1.w);
#pragma unroll
            for (int i = 0; i < 4; i++)
#pragma unroll
                for (int j = 0; j < 8; j++)
                    acc2[i][j] = ffma2(av[i], bd[j], acc2[i][j]);
        }
        __syncthreads();
    }

    // epilogue 2: bias + optional relu -> out (global)
    {
        float4 bb0 = ((const float4*)b2)[tx * 2];
        float4 bb1 = ((const float4*)b2)[tx * 2 + 1];
        float bvv[8] = {bb0.x, bb0.y, bb0.z, bb0.w, bb1.x, bb1.y, bb1.z, bb1.w};
#pragma unroll
        for (int i2 = 0; i2 < 4; i2++) {
            float o0[8], o1[8];
#pragma unroll
            for (int j = 0; j < 8; j++) {
                float lo, hi;
                unpack2(acc2[i2][j], lo, hi);
                lo += bvv[j]; hi += bvv[j];
                if (RELU2) { lo = fmaxf(lo, 0.f); hi = fmaxf(hi, 0.f); }
                o0[j] = lo; o1[j] = hi;
            }
            int r0 = row0 + ty * 8 + 2 * i2;
            if (r0 < M) {
                float4* po = (float4*)(out + (long long)r0 * DD);
                po[tx * 2]     = make_float4(o0[0], o0[1], o0[2], o0[3]);
                po[tx * 2 + 1] = make_float4(o0[4], o0[5], o0[6], o0[7]);
            }
            if (r0 + 1 < M) {
                float4* po = (float4*)(out + (long long)(r0 + 1) * DD);
                po[tx * 2]     = make_float4(o1[0], o1[1], o1[2], o1[3]);
                po[tx * 2 + 1] = make_float4(o1[4], o1[5], o1[6], o1[7]);
            }
        }
    }
}

// ---------------------------------------------------------------------------
extern "C" void kernel_launch(void* const* d_in, const int* in_sizes, int n_in,
                              void* d_out, int out_size) {
    const float* x    = (const float*)d_in[0];
    const int*   ei   = (const int*)d_in[1];      // int32
    const float* ea   = (const float*)d_in[2];
    const float* w1_0 = (const float*)d_in[3];
    const float* b1_0 = (const float*)d_in[4];
    const float* w2_0 = (const float*)d_in[5];
    const float* b2_0 = (const float*)d_in[6];
    const float* we_0 = (const float*)d_in[7];
    const float* be_0 = (const float*)d_in[8];
    const float* w1_1 = (const float*)d_in[9];
    const float* b1_1 = (const float*)d_in[10];
    const float* w2_1 = (const float*)d_in[11];
    const float* b2_1 = (const float*)d_in[12];
    const float* we_1 = (const float*)d_in[13];
    const float* be_1 = (const float*)d_in[14];
    const float* fc1w = (const float*)d_in[15];
    const float* fc1b = (const float*)d_in[16];
    const float* fc2w = (const float*)d_in[17];
    const float* fc2b = (const float*)d_in[18];
    float* out = (float*)d_out;

    float *agg, *h;
    cudaGetSymbolAddress((void**)&agg, g_agg);
    cudaGetSymbolAddress((void**)&h,   g_h);

    cudaFuncSetAttribute(mlp2_gemm<true>,  cudaFuncAttributeMaxDynamicSharedMemorySize, MLP2_SMEM);
    cudaFuncSetAttribute(mlp2_gemm<false>, cudaFuncAttributeMaxDynamicSharedMemorySize, MLP2_SMEM);

    const int n4 = NN * (DD / 4);
    const int copyBlocks = (n4 + 255) / 256;
    const int nodeBlocks = (NN + 255) / 256;
    const int edgeThreadBlocks = (NE + 255) / 256;
    const int permBlocks = (int)(((long long)NE * 8 + 255) / 256);
    const int fusedBlocks = (NE + 127) / 128;
    const int gemmBlocks = (NN + 127) / 128;          // 391

    // ---- CSR build (once; reused by both layers) ----
    zero_cnt_kernel<<<nodeBlocks, 256>>>();
    hist_kernel<<<edgeThreadBlocks, 256>>>(ei);
    scan_kernel<<<1, 1024>>>();
    scatter_kernel<<<edgeThreadBlocks, 256>>>(ei);
    permute_ea_kernel<<<permBlocks, 256>>>((const float4*)ea);

    // ---- Layer 0: agg = x + scatter(relu(x[src]+ea@we)); h = MLP(agg) ----
    copy4_kernel<<<copyBlocks, 256>>>((const float4*)x, (float4*)agg, n4);
    edge_fused_kernel<<<fusedBlocks, 256>>>(x, we_0, be_0, agg);
    mlp2_gemm<true><<<gemmBlocks, 256, MLP2_SMEM>>>(agg, w1_0, b1_0, w2_0, b2_0, h, NN);

    // ---- Layer 1 ----
    copy4_kernel<<<copyBlocks, 256>>>((const float4*)h, (float4*)agg, n4);
    edge_fused_kernel<<<fusedBlocks, 256>>>(h, we_1, be_1, agg);
    mlp2_gemm<true><<<gemmBlocks, 256, MLP2_SMEM>>>(agg, w1_1, b1_1, w2_1, b2_1, h, NN);

    // ---- Head: out = fc2(relu(fc1(h))) ----
    mlp2_gemm<false><<<gemmBlocks, 256, MLP2_SMEM>>>(h, fc1w, fc1b, fc2w, fc2b, out, NN);
}

// round 12
// speedup vs baseline: 2.8829x; 1.1483x over previous
#include <cuda_runtime.h>
#include <cuda_bf16.h>
#include <cstdint>

#define NN 50000
#define NE 600000
#define DD 128
#define DE 32

typedef unsigned long long u64;

// Scratch (device globals — no allocation allowed)
__device__ float g_agg[NN * DD];
__device__ float g_h[NN * DD];
__device__ float g_t[NN * DD];
__device__ float g_eap[(size_t)NE * DE];     // permuted edge_attr (77 MB)
__device__ int   g_rowptr[NN + 1];
__device__ int   g_woff[NN];
__device__ int   g_cnt[NN];
__device__ int   g_srcp[NE];
__device__ int   g_dstp[NE];
__device__ int   g_eidx[NE];

// ---- packed fp32x2 helpers ----
__device__ __forceinline__ u64 ffma2(u64 a, u64 b, u64 c) {
    u64 d;
    asm("fma.rn.f32x2 %0, %1, %2, %3;" : "=l"(d) : "l"(a), "l"(b), "l"(c));
    return d;
}
__device__ __forceinline__ u64 pack2(float lo, float hi) {
    u64 d;
    asm("mov.b64 %0, {%1, %2};" : "=l"(d) : "f"(lo), "f"(hi));
    return d;
}
__device__ __forceinline__ void unpack2(u64 v, float& lo, float& hi) {
    asm("mov.b64 {%0, %1}, %2;" : "=f"(lo), "=f"(hi) : "l"(v));
}

// ===========================================================================
// CSR build (unchanged)
// ===========================================================================
__global__ void zero_cnt_kernel() {
    int i = blockIdx.x * blockDim.x + threadIdx.x;
    if (i < NN) g_cnt[i] = 0;
}

__global__ void hist_kernel(const int* __restrict__ ei) {
    int i = blockIdx.x * blockDim.x + threadIdx.x;
    if (i < NE) atomicAdd(&g_cnt[ei[NE + i]], 1);
}

__global__ void scan_kernel() {
    __shared__ int s[1024];
    const int tid = threadIdx.x;
    const int CH = (NN + 1023) / 1024;
    const int base = tid * CH;
    const int end = min(base + CH, NN);
    int tot = 0;
    for (int i = base; i < end; i++) tot += g_cnt[i];
    s[tid] = tot;
    __syncthreads();
#pragma unroll
    for (int off = 1; off < 1024; off <<= 1) {
        int t = (tid >= off) ? s[tid - off] : 0;
        __syncthreads();
        s[tid] += t;
        __syncthreads();
    }
    int run = s[tid] - tot;
    for (int i = base; i < end; i++) {
        int v = g_cnt[i];
        g_rowptr[i] = run;
        g_woff[i] = run;
        run += v;
    }
    if (end == NN) g_rowptr[NN] = run;
}

__global__ void scatter_kernel(const int* __restrict__ ei) {
    int i = blockIdx.x * blockDim.x + threadIdx.x;
    if (i < NE) {
        int d = ei[NE + i];
        int p = atomicAdd(&g_woff[d], 1);
        g_srcp[p] = ei[i];
        g_dstp[p] = d;
        g_eidx[p] = i;
    }
}

__global__ void permute_ea_kernel(const float4* __restrict__ ea4) {
    long long t = (long long)blockIdx.x * blockDim.x + threadIdx.x;
    if (t < (long long)NE * 8) {
        long long i = t >> 3;
        int c = (int)(t & 7);
        int e = g_eidx[i];
        ((float4*)g_eap)[t] = ea4[(long long)e * 8 + c];
    }
}

// ===========================================================================
// Fused edge kernel (unchanged from R6): GEMM + segmented RED into agg
// ===========================================================================
__global__ void __launch_bounds__(256, 2)
edge_fused_kernel(const float* __restrict__ xin,
                  const float* __restrict__ we, const float* __restrict__ be,
                  float* __restrict__ agg) {
    __shared__ float Ea[DE][130];
    __shared__ float Bs[DE][DD];

    const int tid = threadIdx.x;
    const int tx = tid & 15;
    const int ty = tid >> 4;
    const long long i0 = (long long)blockIdx.x * 128;

#pragma unroll
    for (int l = 0; l < 4; l++) {
        int idx = tid + l * 256;
        int r  = idx >> 3;
        int c4 = idx & 7;
        float4 v = make_float4(0.f, 0.f, 0.f, 0.f);
        long long gi = i0 + r;
        if (gi < NE) v = ((const float4*)g_eap)[gi * 8 + c4];
        Ea[c4 * 4 + 0][r] = v.x;
        Ea[c4 * 4 + 1][r] = v.y;
        Ea[c4 * 4 + 2][r] = v.z;
        Ea[c4 * 4 + 3][r] = v.w;
        ((float4*)&Bs[idx >> 5][0])[idx & 31] = ((const float4*)we)[idx];
    }
    __syncthreads();

    u64 acc2[4][8];
#pragma unroll
    for (int i = 0; i < 4; i++)
#pragma unroll
        for (int j = 0; j < 8; j++) acc2[i][j] = 0ULL;

#pragma unroll 8
    for (int k = 0; k < DE; k++) {
        const u64* ap = (const u64*)&Ea[k][ty * 8];
        u64 av[4] = {ap[0], ap[1], ap[2], ap[3]};
        float4 b0 = ((const float4*)&Bs[k][0])[tx * 2];
        float4 b1 = ((const float4*)&Bs[k][0])[tx * 2 + 1];
        u64 bd[8];
        bd[0] = pack2(b0.x, b0.x); bd[1] = pack2(b0.y, b0.y);
        bd[2] = pack2(b0.z, b0.z); bd[3] = pack2(b0.w, b0.w);
        bd[4] = pack2(b1.x, b1.x); bd[5] = pack2(b1.y, b1.y);
        bd[6] = pack2(b1.z, b1.z); bd[7] = pack2(b1.w, b1.w);
#pragma unroll
        for (int i = 0; i < 4; i++)
#pragma unroll
            for (int j = 0; j < 8; j++)
                acc2[i][j] = ffma2(av[i], bd[j], acc2[i][j]);
    }

    float4 bb0 = ((const float4*)be)[tx * 2];
    float4 bb1 = ((const float4*)be)[tx * 2 + 1];
    float bvv[8] = {bb0.x, bb0.y, bb0.z, bb0.w, bb1.x, bb1.y, bb1.z, bb1.w};

    int d_cur = -1;
    float sum[8];
#pragma unroll
    for (int rr = 0; rr < 8; rr++) {
        long long gi = i0 + ty * 8 + rr;
        if (gi < NE) {
            int d = g_dstp[gi];
            int src = g_srcp[gi];
            int i2 = rr >> 1;
            float o[8];
#pragma unroll
            for (int j = 0; j < 8; j++) {
                float lo, hi;
                unpack2(acc2[i2][j], lo, hi);
                o[j] = (rr & 1) ? hi : lo;
            }
            float4 xv0 = ((const float4*)xin)[(long long)src * 32 + tx * 2];
            float4 xv1 = ((const float4*)xin)[(long long)src * 32 + tx * 2 + 1];
            float xr[8] = {xv0.x, xv0.y, xv0.z, xv0.w, xv1.x, xv1.y, xv1.z, xv1.w};
            float res[8];
#pragma unroll
            for (int j = 0; j < 8; j++)
                res[j] = fmaxf(o[j] + bvv[j] + xr[j], 0.f);
            if (d != d_cur) {
                if (d_cur >= 0) {
                    float* p = agg + (long long)d_cur * DD + tx * 8;
                    asm volatile("red.global.add.v4.f32 [%0], {%1,%2,%3,%4};"
                                 :: "l"(p), "f"(sum[0]), "f"(sum[1]), "f"(sum[2]), "f"(sum[3]) : "memory");
                    asm volatile("red.global.add.v4.f32 [%0], {%1,%2,%3,%4};"
                                 :: "l"(p + 4), "f"(sum[4]), "f"(sum[5]), "f"(sum[6]), "f"(sum[7]) : "memory");
                }
                d_cur = d;
#pragma unroll
                for (int j = 0; j < 8; j++) sum[j] = res[j];
            } else {
#pragma unroll
                for (int j = 0; j < 8; j++) sum[j] += res[j];
            }
        }
    }
    if (d_cur >= 0) {
        float* p = agg + (long long)d_cur * DD + tx * 8;
        asm volatile("red.global.add.v4.f32 [%0], {%1,%2,%3,%4};"
                     :: "l"(p), "f"(sum[0]), "f"(sum[1]), "f"(sum[2]), "f"(sum[3]) : "memory");
        asm volatile("red.global.add.v4.f32 [%0], {%1,%2,%3,%4};"
                     :: "l"(p + 4), "f"(sum[4]), "f"(sum[5]), "f"(sum[6]), "f"(sum[7]) : "memory");
    }
}

__global__ void copy4_kernel(const float4* __restrict__ s, float4* __restrict__ d, int n4) {
    int i = blockIdx.x * blockDim.x + threadIdx.x;
    if (i < n4) d[i] = s[i];
}

// ===========================================================================
// bf16 split-mma node GEMM: out[M,128] = act(A[M,128]@W[128,128] + bias)
// A=Ah+Al, W=Wh+Wl bf16; D = AhWh + AhWl + AlWh via mma.sync.m16n8k16.
// smem: XOR-swizzled [row][k] bf16 tiles (16B-chunk ^ (row&7)) for
// conflict-free ldmatrix. 512 threads, 16 warps; warp (w&7)->m16 tile,
// (w>>3)->64-col half; 8 n-blocks/warp; fp32 accum in registers.
// ===========================================================================
#define S_AH 0
#define S_AL 32768
#define S_WH 65536
#define S_WL 98304
#define S_BIAS 131072
#define S_TOTAL 131584

static __device__ __forceinline__ uint32_t smem_u32(const void* p) {
    uint32_t a;
    asm("{ .reg .u64 t; cvta.to.shared.u64 t, %1; cvt.u32.u64 %0, t; }" : "=r"(a) : "l"(p));
    return a;
}
// byte addr of (row, 16B-chunk c) in a swizzled [128][128]bf16 tile
static __device__ __forceinline__ uint32_t asw(int row, int c) {
    return (uint32_t)(row * 256 + ((c ^ (row & 7)) << 4));
}
static __device__ __forceinline__ uint32_t packbf(float a, float b) {
    __nv_bfloat16 ha = __float2bfloat16_rn(a), hb = __float2bfloat16_rn(b);
    uint16_t ua = *(uint16_t*)&ha, ub = *(uint16_t*)&hb;
    return (uint32_t)ua | ((uint32_t)ub << 16);
}
static __device__ __forceinline__ float bflo(float a) {
    __nv_bfloat16 h = __float2bfloat16_rn(a);
    return a - __bfloat162float(h);
}

#define LDSM_X4(r, a) \
    asm volatile("ldmatrix.sync.aligned.m8n8.x4.shared.b16 {%0,%1,%2,%3}, [%4];" \
        : "=r"((r)[0]), "=r"((r)[1]), "=r"((r)[2]), "=r"((r)[3]) : "r"(a))

__device__ __forceinline__ void mma16816(float* c, const uint32_t* a, uint32_t b0, uint32_t b1) {
    asm volatile("mma.sync.aligned.m16n8k16.row.col.f32.bf16.bf16.f32 "
        "{%0,%1,%2,%3}, {%4,%5,%6,%7}, {%8,%9}, {%0,%1,%2,%3};"
        : "+f"(c[0]), "+f"(c[1]), "+f"(c[2]), "+f"(c[3])
        : "r"(a[0]), "r"(a[1]), "r"(a[2]), "r"(a[3]), "r"(b0), "r"(b1));
}

template <bool RELU>
__global__ void __launch_bounds__(512)
tc_gemm(const float* __restrict__ A, const float* __restrict__ W,
        const float* __restrict__ bias, float* __restrict__ out, int M) {
    extern __shared__ char smem[];
    const uint32_t sb = smem_u32(smem);
    const int tid = threadIdx.x;
    const int row0 = blockIdx.x * 128;

    // ---- convert A tile: fp32 -> Ah/Al swizzled bf16 ----
    for (int idx = tid; idx < 128 * 32; idx += 512) {
        int m = idx >> 5;
        int k4 = idx & 31;               // k = k4*4
        float4 v = make_float4(0.f, 0.f, 0.f, 0.f);
        int gm = row0 + m;
        if (gm < M) v = ((const float4*)A)[(long long)gm * 32 + k4];
        uint32_t off = asw(m, k4 >> 1) + (k4 & 1) * 8;
        *(uint2*)(smem + S_AH + off) = make_uint2(packbf(v.x, v.y), packbf(v.z, v.w));
        *(uint2*)(smem + S_AL + off) = make_uint2(packbf(bflo(v.x), bflo(v.y)),
                                                  packbf(bflo(v.z), bflo(v.w)));
    }
    // ---- convert W: [k][n] fp32 -> [n][k] Wh/Wl swizzled bf16 ----
    for (int idx = tid; idx < 128 * 32; idx += 512) {
        int n = idx & 127;
        int kq = idx >> 7;               // k = kq*4
        int k = kq * 4;
        float w0 = W[(k + 0) * 128 + n];
        float w1 = W[(k + 1) * 128 + n];
        float w2 = W[(k + 2) * 128 + n];
        float w3 = W[(k + 3) * 128 + n];
        uint32_t off = asw(n, kq >> 1) + (kq & 1) * 8;
        *(uint2*)(smem + S_WH + off) = make_uint2(packbf(w0, w1), packbf(w2, w3));
        *(uint2*)(smem + S_WL + off) = make_uint2(packbf(bflo(w0), bflo(w1)),
                                                  packbf(bflo(w2), bflo(w3)));
    }
    if (tid < 128) ((float*)(smem + S_BIAS))[tid] = bias[tid];
    __syncthreads();

    // ---- compute ----
    const int w = tid >> 5;
    const int lane = tid & 31;
    const int m0 = (w & 7) * 16;
    const int nbase = (w >> 3) * 64;

    float c[8][4];
#pragma unroll
    for (int j = 0; j < 8; j++)
#pragma unroll
        for (int q = 0; q < 4; q++) c[j][q] = 0.f;

    // ldmatrix lane-address components
    const int ar = m0 + (lane & 15);             // A row for this lane
    const int ak = (lane >> 4);                  // 0/1: k 16B-half
    const int br = (lane & 7) + ((lane >> 4) << 3);  // n-row offset within pair
    const int bk = (lane >> 3) & 1;              // k 16B-half

#pragma unroll
    for (int kc = 0; kc < 8; kc++) {
        uint32_t ah[4], al[4];
        uint32_t aaddr = asw(ar, kc * 2 + ak);
        LDSM_X4(ah, sb + S_AH + aaddr);
        LDSM_X4(al, sb + S_AL + aaddr);
#pragma unroll
        for (int jp = 0; jp < 4; jp++) {
            int nrow = nbase + jp * 16 + br;
            uint32_t baddr = asw(nrow, kc * 2 + bk);
            uint32_t bh[4], bl[4];
            LDSM_X4(bh, sb + S_WH + baddr);
            LDSM_X4(bl, sb + S_WL + baddr);
            mma16816(c[jp * 2],     ah, bh[0], bh[1]);
            mma16816(c[jp * 2],     ah, bl[0], bl[1]);
            mma16816(c[jp * 2],     al, bh[0], bh[1]);
            mma16816(c[jp * 2 + 1], ah, bh[2], bh[3]);
            mma16816(c[jp * 2 + 1], ah, bl[2], bl[3]);
            mma16816(c[jp * 2 + 1], al, bh[2], bh[3]);
        }
    }

    // ---- epilogue ----
    const int g = lane >> 2;
    const int tig = lane & 3;
    const int rlo = row0 + m0 + g;
    const int rhi = rlo + 8;
    const float* bs = (const float*)(smem + S_BIAS);
#pragma unroll
    for (int j = 0; j < 8; j++) {
        int n0 = nbase + j * 8 + tig * 2;
        float bb0 = bs[n0], bb1 = bs[n0 + 1];
        float v0 = c[j][0] + bb0, v1 = c[j][1] + bb1;
        float v2 = c[j][2] + bb0, v3 = c[j][3] + bb1;
        if (RELU) {
            v0 = fmaxf(v0, 0.f); v1 = fmaxf(v1, 0.f);
            v2 = fmaxf(v2, 0.f); v3 = fmaxf(v3, 0.f);
        }
        if (rlo < M) *(float2*)(out + (long long)rlo * DD + n0) = make_float2(v0, v1);
        if (rhi < M) *(float2*)(out + (long long)rhi * DD + n0) = make_float2(v2, v3);
    }
}

// ---------------------------------------------------------------------------
extern "C" void kernel_launch(void* const* d_in, const int* in_sizes, int n_in,
                              void* d_out, int out_size) {
    const float* x    = (const float*)d_in[0];
    const int*   ei   = (const int*)d_in[1];      // int32
    const float* ea   = (const float*)d_in[2];
    const float* w1_0 = (const float*)d_in[3];
    const float* b1_0 = (const float*)d_in[4];
    const float* w2_0 = (const float*)d_in[5];
    const float* b2_0 = (const float*)d_in[6];
    const float* we_0 = (const float*)d_in[7];
    const float* be_0 = (const float*)d_in[8];
    const float* w1_1 = (const float*)d_in[9];
    const float* b1_1 = (const float*)d_in[10];
    const float* w2_1 = (const float*)d_in[11];
    const float* b2_1 = (const float*)d_in[12];
    const float* we_1 = (const float*)d_in[13];
    const float* be_1 = (const float*)d_in[14];
    const float* fc1w = (const float*)d_in[15];
    const float* fc1b = (const float*)d_in[16];
    const float* fc2w = (const float*)d_in[17];
    const float* fc2b = (const float*)d_in[18];
    float* out = (float*)d_out;

    float *agg, *h, *t;
    cudaGetSymbolAddress((void**)&agg, g_agg);
    cudaGetSymbolAddress((void**)&h,   g_h);
    cudaGetSymbolAddress((void**)&t,   g_t);

    cudaFuncSetAttribute(tc_gemm<true>,  cudaFuncAttributeMaxDynamicSharedMemorySize, S_TOTAL);
    cudaFuncSetAttribute(tc_gemm<false>, cudaFuncAttributeMaxDynamicSharedMemorySize, S_TOTAL);

    const int n4 = NN * (DD / 4);
    const int copyBlocks = (n4 + 255) / 256;
    const int nodeBlocks = (NN + 255) / 256;
    const int edgeThreadBlocks = (NE + 255) / 256;
    const int permBlocks = (int)(((long long)NE * 8 + 255) / 256);
    const int fusedBlocks = (NE + 127) / 128;
    const int gemmBlocks = (NN + 127) / 128;          // 391

    // ---- CSR build (once; reused by both layers) ----
    zero_cnt_kernel<<<nodeBlocks, 256>>>();
    hist_kernel<<<edgeThreadBlocks, 256>>>(ei);
    scan_kernel<<<1, 1024>>>();
    scatter_kernel<<<edgeThreadBlocks, 256>>>(ei);
    permute_ea_kernel<<<permBlocks, 256>>>((const float4*)ea);

    // ---- Layer 0 ----
    copy4_kernel<<<copyBlocks, 256>>>((const float4*)x, (float4*)agg, n4);
    edge_fused_kernel<<<fusedBlocks, 256>>>(x, we_0, be_0, agg);
    tc_gemm<true><<<gemmBlocks, 512, S_TOTAL>>>(agg, w1_0, b1_0, t, NN);
    tc_gemm<true><<<gemmBlocks, 512, S_TOTAL>>>(t, w2_0, b2_0, h, NN);

    // ---- Layer 1 ----
    copy4_kernel<<<copyBlocks, 256>>>((const float4*)h, (float4*)agg, n4);
    edge_fused_kernel<<<fusedBlocks, 256>>>(h, we_1, be_1, agg);
    tc_gemm<true><<<gemmBlocks, 512, S_TOTAL>>>(agg, w1_1, b1_1, t, NN);
    tc_gemm<true><<<gemmBlocks, 512, S_TOTAL>>>(t, w2_1, b2_1, h, NN);

    // ---- Head ----
    tc_gemm<true><<<gemmBlocks, 512, S_TOTAL>>>(h, fc1w, fc1b, t, NN);
    tc_gemm<false><<<gemmBlocks, 512, S_TOTAL>>>(t, fc2w, fc2b, out, NN);
}

// round 13
// speedup vs baseline: 3.0887x; 1.0714x over previous
#include <cuda_runtime.h>
#include <cuda_bf16.h>
#include <cstdint>

#define NN 50000
#define NE 600000
#define DD 128
#define DE 32

typedef unsigned long long u64;

// Scratch (device globals — no allocation allowed)
__device__ float g_agg[NN * DD];
__device__ float g_h[NN * DD];
__device__ float g_t[NN * DD];
__device__ int   g_rowptr[NN + 1];
__device__ int   g_woff[NN];
__device__ int   g_cnt[NN];
__device__ int   g_srcp[NE];
__device__ int   g_dstp[NE];
__device__ int   g_eidx[NE];
// pre-converted operands
__device__ __nv_bfloat16 g_eaH[(size_t)NE * DE];   // permuted edge_attr hi
__device__ __nv_bfloat16 g_eaL[(size_t)NE * DE];   // permuted edge_attr lo
__device__ __nv_bfloat16 g_wtH[6][DD * DD];        // node W transposed [n][k] hi
__device__ __nv_bfloat16 g_wtL[6][DD * DD];
__device__ __nv_bfloat16 g_weH[2][DD * DE];        // edge we transposed [n][k] hi
__device__ __nv_bfloat16 g_weL[2][DD * DE];

// ---- helpers ----
static __device__ __forceinline__ uint32_t smem_u32(const void* p) {
    uint32_t a;
    asm("{ .reg .u64 t; cvta.to.shared.u64 t, %1; cvt.u32.u64 %0, t; }" : "=r"(a) : "l"(p));
    return a;
}
static __device__ __forceinline__ uint32_t packbf(float a, float b) {
    __nv_bfloat16 ha = __float2bfloat16_rn(a), hb = __float2bfloat16_rn(b);
    uint16_t ua = *(uint16_t*)&ha, ub = *(uint16_t*)&hb;
    return (uint32_t)ua | ((uint32_t)ub << 16);
}
static __device__ __forceinline__ float bflo(float a) {
    __nv_bfloat16 h = __float2bfloat16_rn(a);
    return a - __bfloat162float(h);
}
// swizzled byte addr: 256B rows (128 bf16), chunk c in 0..15
static __device__ __forceinline__ uint32_t asw(int row, int c) {
    return (uint32_t)(row * 256 + ((c ^ (row & 7)) << 4));
}
// swizzled byte addr: 128B rows (64 bf16 = hi32|lo32), chunk c in 0..7
static __device__ __forceinline__ uint32_t asw128(int row, int c) {
    return (uint32_t)(row * 128 + ((c ^ (row & 7)) << 4));
}

#define LDSM_X4(r, a) \
    asm volatile("ldmatrix.sync.aligned.m8n8.x4.shared.b16 {%0,%1,%2,%3}, [%4];" \
        : "=r"((r)[0]), "=r"((r)[1]), "=r"((r)[2]), "=r"((r)[3]) : "r"(a))

__device__ __forceinline__ void mma16816(float* c, const uint32_t* a, uint32_t b0, uint32_t b1) {
    asm volatile("mma.sync.aligned.m16n8k16.row.col.f32.bf16.bf16.f32 "
        "{%0,%1,%2,%3}, {%4,%5,%6,%7}, {%8,%9}, {%0,%1,%2,%3};"
        : "+f"(c[0]), "+f"(c[1]), "+f"(c[2]), "+f"(c[3])
        : "r"(a[0]), "r"(a[1]), "r"(a[2]), "r"(a[3]), "r"(b0), "r"(b1));
}

// ===========================================================================
// CSR build
// ===========================================================================
__global__ void zero_cnt_kernel() {
    int i = blockIdx.x * blockDim.x + threadIdx.x;
    if (i < NN) g_cnt[i] = 0;
}

__global__ void hist_kernel(const int* __restrict__ ei) {
    int i = blockIdx.x * blockDim.x + threadIdx.x;
    if (i < NE) atomicAdd(&g_cnt[ei[NE + i]], 1);
}

__global__ void scan_kernel() {
    __shared__ int s[1024];
    const int tid = threadIdx.x;
    const int CH = (NN + 1023) / 1024;
    const int base = tid * CH;
    const int end = min(base + CH, NN);
    int tot = 0;
    for (int i = base; i < end; i++) tot += g_cnt[i];
    s[tid] = tot;
    __syncthreads();
#pragma unroll
    for (int off = 1; off < 1024; off <<= 1) {
        int t = (tid >= off) ? s[tid - off] : 0;
        __syncthreads();
        s[tid] += t;
        __syncthreads();
    }
    int run = s[tid] - tot;
    for (int i = base; i < end; i++) {
        int v = g_cnt[i];
        g_rowptr[i] = run;
        g_woff[i] = run;
        run += v;
    }
    if (end == NN) g_rowptr[NN] = run;
}

__global__ void scatter_kernel(const int* __restrict__ ei) {
    int i = blockIdx.x * blockDim.x + threadIdx.x;
    if (i < NE) {
        int d = ei[NE + i];
        int p = atomicAdd(&g_woff[d], 1);
        g_srcp[p] = ei[i];
        g_dstp[p] = d;
        g_eidx[p] = i;
    }
}

// permute + convert edge_attr to bf16 hi/lo (64B rows)
__global__ void conv_ea_kernel(const float4* __restrict__ ea4) {
    long long t = (long long)blockIdx.x * blockDim.x + threadIdx.x;
    if (t < (long long)NE * 4) {
        long long i = t >> 2;
        int c = (int)(t & 3);
        int e = g_eidx[i];
        float4 v0 = ea4[(long long)e * 8 + c * 2];
        float4 v1 = ea4[(long long)e * 8 + c * 2 + 1];
        uint4 hi = make_uint4(packbf(v0.x, v0.y), packbf(v0.z, v0.w),
                              packbf(v1.x, v1.y), packbf(v1.z, v1.w));
        uint4 lo = make_uint4(packbf(bflo(v0.x), bflo(v0.y)), packbf(bflo(v0.z), bflo(v0.w)),
                              packbf(bflo(v1.x), bflo(v1.y)), packbf(bflo(v1.z), bflo(v1.w)));
        *(uint4*)((char*)g_eaH + i * 64 + c * 16) = hi;
        *(uint4*)((char*)g_eaL + i * 64 + c * 16) = lo;
    }
}

// node W [k128][n128] fp32 -> transposed [n][k] bf16 hi/lo
__global__ void conv_w_kernel(const float* __restrict__ W,
                              __nv_bfloat16* __restrict__ dh,
                              __nv_bfloat16* __restrict__ dl) {
    int idx = blockIdx.x * blockDim.x + threadIdx.x;   // < 128*32
    if (idx < 128 * 32) {
        int n = idx & 127;
        int kq = idx >> 7;
        float w0 = W[(kq * 4 + 0) * 128 + n];
        float w1 = W[(kq * 4 + 1) * 128 + n];
        float w2 = W[(kq * 4 + 2) * 128 + n];
        float w3 = W[(kq * 4 + 3) * 128 + n];
        *(uint2*)(dh + n * 128 + kq * 4) = make_uint2(packbf(w0, w1), packbf(w2, w3));
        *(uint2*)(dl + n * 128 + kq * 4) = make_uint2(packbf(bflo(w0), bflo(w1)), packbf(bflo(w2), bflo(w3)));
    }
}

// edge we [k32][n128] fp32 -> transposed [n][k32] bf16 hi/lo
__global__ void conv_we_kernel(const float* __restrict__ W,
                               __nv_bfloat16* __restrict__ dh,
                               __nv_bfloat16* __restrict__ dl) {
    int idx = blockIdx.x * blockDim.x + threadIdx.x;   // < 128*8
    if (idx < 128 * 8) {
        int n = idx & 127;
        int kq = idx >> 7;
        float w0 = W[(kq * 4 + 0) * 128 + n];
        float w1 = W[(kq * 4 + 1) * 128 + n];
        float w2 = W[(kq * 4 + 2) * 128 + n];
        float w3 = W[(kq * 4 + 3) * 128 + n];
        *(uint2*)(dh + n * 32 + kq * 4) = make_uint2(packbf(w0, w1), packbf(w2, w3));
        *(uint2*)(dl + n * 32 + kq * 4) = make_uint2(packbf(bflo(w0), bflo(w1)), packbf(bflo(w2), bflo(w3)));
    }
}

__global__ void copy4_kernel(const float4* __restrict__ s, float4* __restrict__ d, int n4) {
    int i = blockIdx.x * blockDim.x + threadIdx.x;
    if (i < n4) d[i] = s[i];
}

// ===========================================================================
// Edge kernel (mma): emb = ea@we via bf16-split mma -> Msg smem;
// epilogue = R6 segmented reduction (relu(emb+be+x[src]) summed per dst run).
// 256 threads, 8 warps; warp w -> m16 tile, all 128 n. Edges CSR-sorted.
// ===========================================================================
#define E_EA  0
#define E_WE  16384
#define E_MSG 32768
#define E_TOTAL (32768 + 128 * 528)      // 100352
#define MSG_STRIDE 132                   // floats; 528B rows

__global__ void __launch_bounds__(256, 2)
edge_fused_kernel(const float* __restrict__ xin,
                  const __nv_bfloat16* __restrict__ weH,
                  const __nv_bfloat16* __restrict__ weL,
                  const float* __restrict__ be,
                  float* __restrict__ agg) {
    extern __shared__ char smem[];
    const uint32_t sb = smem_u32(smem);
    float* MsgS = (float*)(smem + E_MSG);
    const int tid = threadIdx.x;
    const long long i0 = (long long)blockIdx.x * 128;

    // load Ea tile (hi|lo 128B rows, swizzled) + We tile
#pragma unroll
    for (int l = 0; l < 4; l++) {
        int idx = tid + l * 256;          // 0..1023 : Ea
        int r = idx >> 3;
        int c = idx & 7;
        long long gi = i0 + r;
        uint4 v = make_uint4(0, 0, 0, 0);
        if (gi < NE) {
            const char* src = (c < 4) ? ((const char*)g_eaH + gi * 64 + c * 16)
                                      : ((const char*)g_eaL + gi * 64 + (c - 4) * 16);
            v = *(const uint4*)src;
        }
        *(uint4*)(smem + E_EA + asw128(r, c)) = v;
        // We
        const char* ws = (c < 4) ? ((const char*)weH + r * 64 + c * 16)
                                 : ((const char*)weL + r * 64 + (c - 4) * 16);
        *(uint4*)(smem + E_WE + asw128(r, c)) = *(const uint4*)ws;
    }
    __syncthreads();

    // ---- mma: 8 warps, warp w -> rows [w*16, w*16+16), cols 0..127 ----
    {
        const int w = tid >> 5;
        const int lane = tid & 31;
        const int m0 = w * 16;
        const int ar = m0 + (lane & 15);
        const int ak = lane >> 4;
        const int br = (lane & 7) + ((lane >> 4) << 3);
        const int bk = (lane >> 3) & 1;

        float c[16][4];
#pragma unroll
        for (int j = 0; j < 16; j++)
#pragma unroll
            for (int q = 0; q < 4; q++) c[j][q] = 0.f;

#pragma unroll
        for (int s = 0; s < 2; s++) {
            uint32_t ah[4], al[4];
            LDSM_X4(ah, sb + E_EA + asw128(ar, 2 * s + ak));
            LDSM_X4(al, sb + E_EA + asw128(ar, 4 + 2 * s + ak));
#pragma unroll
            for (int jp = 0; jp < 8; jp++) {
                int nrow = jp * 16 + br;
                uint32_t bh[4], bl[4];
                LDSM_X4(bh, sb + E_WE + asw128(nrow, 2 * s + bk));
                LDSM_X4(bl, sb + E_WE + asw128(nrow, 4 + 2 * s + bk));
                mma16816(c[jp * 2],     ah, bh[0], bh[1]);
                mma16816(c[jp * 2],     ah, bl[0], bl[1]);
                mma16816(c[jp * 2],     al, bh[0], bh[1]);
                mma16816(c[jp * 2 + 1], ah, bh[2], bh[3]);
                mma16816(c[jp * 2 + 1], ah, bl[2], bl[3]);
                mma16816(c[jp * 2 + 1], al, bh[2], bh[3]);
            }
        }
        // park emb in Msg smem (row-major, padded rows)
        const int g = lane >> 2;
        const int tig = lane & 3;
#pragma unroll
        for (int j = 0; j < 16; j++) {
            int col = j * 8 + tig * 2;
            *(float2*)(MsgS + (m0 + g) * MSG_STRIDE + col)     = make_float2(c[j][0], c[j][1]);
            *(float2*)(MsgS + (m0 + g + 8) * MSG_STRIDE + col) = make_float2(c[j][2], c[j][3]);
        }
    }
    __syncthreads();

    // ---- epilogue: segmented reduction over dst runs (cols tx*4 and 64+tx*4) ----
    const int tx = tid & 15;
    const int ty = tid >> 4;
    float4 bvA = *(const float4*)(be + tx * 4);
    float4 bvB = *(const float4*)(be + 64 + tx * 4);
    float bvv[8] = {bvA.x, bvA.y, bvA.z, bvA.w, bvB.x, bvB.y, bvB.z, bvB.w};

    int d_cur = -1;
    float sum[8];
#pragma unroll
    for (int rr = 0; rr < 8; rr++) {
        long long gi = i0 + ty * 8 + rr;
        if (gi < NE) {
            int d = g_dstp[gi];
            int src = g_srcp[gi];
            int row = ty * 8 + rr;
            float4 oA = *(const float4*)(MsgS + row * MSG_STRIDE + tx * 4);
            float4 oB = *(const float4*)(MsgS + row * MSG_STRIDE + 64 + tx * 4);
            float o[8] = {oA.x, oA.y, oA.z, oA.w, oB.x, oB.y, oB.z, oB.w};
            float4 xA = ((const float4*)xin)[(long long)src * 32 + tx];
            float4 xB = ((const float4*)xin)[(long long)src * 32 + 16 + tx];
            float xr[8] = {xA.x, xA.y, xA.z, xA.w, xB.x, xB.y, xB.z, xB.w};
            float res[8];
#pragma unroll
            for (int j = 0; j < 8; j++)
                res[j] = fmaxf(o[j] + bvv[j] + xr[j], 0.f);
            if (d != d_cur) {
                if (d_cur >= 0) {
                    float* p = agg + (long long)d_cur * DD + tx * 4;
                    asm volatile("red.global.add.v4.f32 [%0], {%1,%2,%3,%4};"
                                 :: "l"(p), "f"(sum[0]), "f"(sum[1]), "f"(sum[2]), "f"(sum[3]) : "memory");
                    asm volatile("red.global.add.v4.f32 [%0], {%1,%2,%3,%4};"
                                 :: "l"(p + 64), "f"(sum[4]), "f"(sum[5]), "f"(sum[6]), "f"(sum[7]) : "memory");
                }
                d_cur = d;
#pragma unroll
                for (int j = 0; j < 8; j++) sum[j] = res[j];
            } else {
#pragma unroll
                for (int j = 0; j < 8; j++) sum[j] += res[j];
            }
        }
    }
    if (d_cur >= 0) {
        float* p = agg + (long long)d_cur * DD + tx * 4;
        asm volatile("red.global.add.v4.f32 [%0], {%1,%2,%3,%4};"
                     :: "l"(p), "f"(sum[0]), "f"(sum[1]), "f"(sum[2]), "f"(sum[3]) : "memory");
        asm volatile("red.global.add.v4.f32 [%0], {%1,%2,%3,%4};"
                     :: "l"(p + 64), "f"(sum[4]), "f"(sum[5]), "f"(sum[6]), "f"(sum[7]) : "memory");
    }
}

// ===========================================================================
// bf16 split-mma node GEMM (M=64 tiles, pre-converted W):
// out[M,128] = act(A[M,128]@W + bias). 512 threads, 16 warps:
// w&3 -> m16 tile, w>>2 -> n32 quarter. 2 CTAs/SM.
// ===========================================================================
#define S_AH 0
#define S_AL 16384
#define S_WH 32768
#define S_WL 65536
#define S_BIAS 98304
#define S_TOTAL 98816

template <bool RELU>
__global__ void __launch_bounds__(512, 2)
tc_gemm(const float* __restrict__ A,
        const __nv_bfloat16* __restrict__ wtH, const __nv_bfloat16* __restrict__ wtL,
        const float* __restrict__ bias, float* __restrict__ out, int M) {
    extern __shared__ char smem[];
    const uint32_t sb = smem_u32(smem);
    const int tid = threadIdx.x;
    const int row0 = blockIdx.x * 64;

    // convert A (64 rows) -> swizzled bf16 hi/lo
    for (int idx = tid; idx < 64 * 32; idx += 512) {
        int m = idx >> 5;
        int k4 = idx & 31;
        float4 v = make_float4(0.f, 0.f, 0.f, 0.f);
        int gm = row0 + m;
        if (gm < M) v = ((const float4*)A)[(long long)gm * 32 + k4];
        uint32_t off = asw(m, k4 >> 1) + (k4 & 1) * 8;
        *(uint2*)(smem + S_AH + off) = make_uint2(packbf(v.x, v.y), packbf(v.z, v.w));
        *(uint2*)(smem + S_AL + off) = make_uint2(packbf(bflo(v.x), bflo(v.y)),
                                                  packbf(bflo(v.z), bflo(v.w)));
    }
    // copy pre-converted W tiles (swizzle at store)
    for (int idx = tid; idx < 128 * 16 * 2; idx += 512) {
        int half = idx >> 11;              // 0 = WH, 1 = WL
        int q = idx & 2047;
        int n = q >> 4;
        int c = q & 15;
        const __nv_bfloat16* src = half ? wtL : wtH;
        uint4 v = *(const uint4*)((const char*)(src + n * 128) + c * 16);
        *(uint4*)(smem + (half ? S_WL : S_WH) + asw(n, c)) = v;
    }
    if (tid < 128) ((float*)(smem + S_BIAS))[tid] = bias[tid];
    __syncthreads();

    const int w = tid >> 5;
    const int lane = tid & 31;
    const int m0 = (w & 3) * 16;
    const int nbase = (w >> 2) * 32;

    float c[4][4];
#pragma unroll
    for (int j = 0; j < 4; j++)
#pragma unroll
        for (int q = 0; q < 4; q++) c[j][q] = 0.f;

    const int ar = m0 + (lane & 15);
    const int ak = lane >> 4;
    const int br = (lane & 7) + ((lane >> 4) << 3);
    const int bk = (lane >> 3) & 1;

#pragma unroll
    for (int kc = 0; kc < 8; kc++) {
        uint32_t ah[4], al[4];
        uint32_t aaddr = asw(ar, kc * 2 + ak);
        LDSM_X4(ah, sb + S_AH + aaddr);
        LDSM_X4(al, sb + S_AL + aaddr);
#pragma unroll
        for (int jp = 0; jp < 2; jp++) {
            int nrow = nbase + jp * 16 + br;
            uint32_t baddr = asw(nrow, kc * 2 + bk);
            uint32_t bh[4], bl[4];
            LDSM_X4(bh, sb + S_WH + baddr);
            LDSM_X4(bl, sb + S_WL + baddr);
            mma16816(c[jp * 2],     ah, bh[0], bh[1]);
            mma16816(c[jp * 2],     ah, bl[0], bl[1]);
            mma16816(c[jp * 2],     al, bh[0], bh[1]);
            mma16816(c[jp * 2 + 1], ah, bh[2], bh[3]);
            mma16816(c[jp * 2 + 1], ah, bl[2], bl[3]);
            mma16816(c[jp * 2 + 1], al, bh[2], bh[3]);
        }
    }

    const int g = lane >> 2;
    const int tig = lane & 3;
    const int rlo = row0 + m0 + g;
    const int rhi = rlo + 8;
    const float* bs = (const float*)(smem + S_BIAS);
#pragma unroll
    for (int j = 0; j < 4; j++) {
        int n0 = nbase + j * 8 + tig * 2;
        float bb0 = bs[n0], bb1 = bs[n0 + 1];
        float v0 = c[j][0] + bb0, v1 = c[j][1] + bb1;
        float v2 = c[j][2] + bb0, v3 = c[j][3] + bb1;
        if (RELU) {
            v0 = fmaxf(v0, 0.f); v1 = fmaxf(v1, 0.f);
            v2 = fmaxf(v2, 0.f); v3 = fmaxf(v3, 0.f);
        }
        if (rlo < M) *(float2*)(out + (long long)rlo * DD + n0) = make_float2(v0, v1);
        if (rhi < M) *(float2*)(out + (long long)rhi * DD + n0) = make_float2(v2, v3);
    }
}

// ---------------------------------------------------------------------------
extern "C" void kernel_launch(void* const* d_in, const int* in_sizes, int n_in,
                              void* d_out, int out_size) {
    const float* x    = (const float*)d_in[0];
    const int*   ei   = (const int*)d_in[1];      // int32
    const float* ea   = (const float*)d_in[2];
    const float* w1_0 = (const float*)d_in[3];
    const float* b1_0 = (const float*)d_in[4];
    const float* w2_0 = (const float*)d_in[5];
    const float* b2_0 = (const float*)d_in[6];
    const float* we_0 = (const float*)d_in[7];
    const float* be_0 = (const float*)d_in[8];
    const float* w1_1 = (const float*)d_in[9];
    const float* b1_1 = (const float*)d_in[10];
    const float* w2_1 = (const float*)d_in[11];
    const float* b2_1 = (const float*)d_in[12];
    const float* we_1 = (const float*)d_in[13];
    const float* be_1 = (const float*)d_in[14];
    const float* fc1w = (const float*)d_in[15];
    const float* fc1b = (const float*)d_in[16];
    const float* fc2w = (const float*)d_in[17];
    const float* fc2b = (const float*)d_in[18];
    float* out = (float*)d_out;

    float *agg, *h, *t;
    cudaGetSymbolAddress((void**)&agg, g_agg);
    cudaGetSymbolAddress((void**)&h,   g_h);
    cudaGetSymbolAddress((void**)&t,   g_t);
    __nv_bfloat16 *wtH, *wtL, *weH, *weL;
    cudaGetSymbolAddress((void**)&wtH, g_wtH);
    cudaGetSymbolAddress((void**)&wtL, g_wtL);
    cudaGetSymbolAddress((void**)&weH, g_weH);
    cudaGetSymbolAddress((void**)&weL, g_weL);

    cudaFuncSetAttribute(tc_gemm<true>,  cudaFuncAttributeMaxDynamicSharedMemorySize, S_TOTAL);
    cudaFuncSetAttribute(tc_gemm<false>, cudaFuncAttributeMaxDynamicSharedMemorySize, S_TOTAL);
    cudaFuncSetAttribute(edge_fused_kernel, cudaFuncAttributeMaxDynamicSharedMemorySize, E_TOTAL);

    const int n4 = NN * (DD / 4);
    const int copyBlocks = (n4 + 255) / 256;
    const int nodeBlocks = (NN + 255) / 256;
    const int edgeThreadBlocks = (NE + 255) / 256;
    const int convEaBlocks = (int)(((long long)NE * 4 + 255) / 256);
    const int fusedBlocks = (NE + 127) / 128;         // 4688
    const int tcBlocks = (NN + 63) / 64;              // 782

    // ---- weight pre-conversion ----
    const float* wsrc[6] = {w1_0, w2_0, w1_1, w2_1, fc1w, fc2w};
    for (int i = 0; i < 6; i++)
        conv_w_kernel<<<16, 256>>>(wsrc[i], wtH + i * DD * DD, wtL + i * DD * DD);
    conv_we_kernel<<<4, 256>>>(we_0, weH, weL);
    conv_we_kernel<<<4, 256>>>(we_1, weH + DD * DE, weL + DD * DE);

    // ---- CSR build ----
    zero_cnt_kernel<<<nodeBlocks, 256>>>();
    hist_kernel<<<edgeThreadBlocks, 256>>>(ei);
    scan_kernel<<<1, 1024>>>();
    scatter_kernel<<<edgeThreadBlocks, 256>>>(ei);
    conv_ea_kernel<<<convEaBlocks, 256>>>((const float4*)ea);

    // ---- Layer 0 ----
    copy4_kernel<<<copyBlocks, 256>>>((const float4*)x, (float4*)agg, n4);
    edge_fused_kernel<<<fusedBlocks, 256, E_TOTAL>>>(x, weH, weL, be_0, agg);
    tc_gemm<true><<<tcBlocks, 512, S_TOTAL>>>(agg, wtH + 0 * DD * DD, wtL + 0 * DD * DD, b1_0, t, NN);
    tc_gemm<true><<<tcBlocks, 512, S_TOTAL>>>(t,   wtH + 1 * DD * DD, wtL + 1 * DD * DD, b2_0, h, NN);

    // ---- Layer 1 ----
    copy4_kernel<<<copyBlocks, 256>>>((const float4*)h, (float4*)agg, n4);
    edge_fused_kernel<<<fusedBlocks, 256, E_TOTAL>>>(h, weH + DD * DE, weL + DD * DE, be_1, agg);
    tc_gemm<true><<<tcBlocks, 512, S_TOTAL>>>(agg, wtH + 2 * DD * DD, wtL + 2 * DD * DD, b1_1, t, NN);
    tc_gemm<true><<<tcBlocks, 512, S_TOTAL>>>(t,   wtH + 3 * DD * DD, wtL + 3 * DD * DD, b2_1, h, NN);

    // ---- Head ----
    tc_gemm<true><<<tcBlocks, 512, S_TOTAL>>>(h,  wtH + 4 * DD * DD, wtL + 4 * DD * DD, fc1b, t, NN);
    tc_gemm<false><<<tcBlocks, 512, S_TOTAL>>>(t, wtH + 5 * DD * DD, wtL + 5 * DD * DD, fc2b, out, NN);
}